// round 1
// baseline (speedup 1.0000x reference)
#include <cuda_runtime.h>

// MeanShift: B=2, C=3, H=W=96 -> N=9216 points per batch, 5 iterations.
// y_{t+1}[i] = sum_j w_ij x_j / sum_j w_ij,  w_ij = exp(-||y_i - x_j||^2 * 50)
//
// Key identity (per-query factor cancels in the ratio, but is kept to avoid
// fp32 range overflow):
//   w_ij = exp2( (2g*y_i) . x_j  +  (-g*||x_j||^2)  +  (-g*||y_i||^2) ),
//   g = 50/ln(2) = 72.134752...
// The -g*||x_j||^2 term is precomputed per point; the dot product + 4
// accumulators run two j's at a time via fma.rn.f32x2 (packed fp32),
// keeping the FMA pipe at ~4 instr/pair so the MUFU EX2 (1/pair) binds.

#define NPTS 9216
#define NB 2
#define GG 72.13475204444817f   // 50 / ln(2)

typedef unsigned long long u64;

// Scratch (no allocs allowed): point data in pair-interleaved layout + y ping-pong.
__device__ float4 g_pts[NB * NPTS];      // [b][2*jp+0]={x0,x1,y0,y1}, [b][2*jp+1]={z0,z1,b0,b1}
__device__ float4 g_y[2][NB * NPTS];

__device__ __forceinline__ float ex2f(float x) {
    float r; asm("ex2.approx.ftz.f32 %0, %1;" : "=f"(r) : "f"(x)); return r;
}
__device__ __forceinline__ u64 pk2(float a, float b) {
    u64 r; asm("mov.b64 %0, {%1,%2};" : "=l"(r) : "f"(a), "f"(b)); return r;
}
__device__ __forceinline__ void upk2(u64 v, float& a, float& b) {
    asm("mov.b64 {%0,%1}, %2;" : "=f"(a), "=f"(b) : "l"(v));
}
__device__ __forceinline__ u64 fma2(u64 a, u64 b, u64 c) {
    u64 d; asm("fma.rn.f32x2 %0, %1, %2, %3;" : "=l"(d) : "l"(a), "l"(b), "l"(c)); return d;
}
__device__ __forceinline__ u64 add2(u64 a, u64 b) {
    u64 d; asm("add.rn.f32x2 %0, %1, %2;" : "=l"(d) : "l"(a), "l"(b)); return d;
}

__global__ void prep_kernel(const float* __restrict__ x) {
    int idx = blockIdx.x * blockDim.x + threadIdx.x;
    if (idx >= NB * NPTS) return;
    int b = idx / NPTS, n = idx - b * NPTS;
    float px = x[(b * 3 + 0) * NPTS + n];
    float py = x[(b * 3 + 1) * NPTS + n];
    float pz = x[(b * 3 + 2) * NPTS + n];
    float bn = -GG * (px * px + py * py + pz * pz);
    int jp = n >> 1, l = n & 1;
    float* base = (float*)&g_pts[b * NPTS + 2 * jp];
    base[0 + l] = px;   // {x0,x1, y0,y1}
    base[2 + l] = py;
    base[4 + l] = pz;   // {z0,z1, b0,b1}
    base[6 + l] = bn;
    g_y[0][b * NPTS + n] = make_float4(px, py, pz, 0.f);
}

// Grid: (72 query-tiles, 2 batches). 256 threads = 128 queries x 2 j-splits.
// Each SM gets ~1 block; 2 warps/SMSP hide MUFU(16cyc)/LDS(29cyc) latency.
__global__ __launch_bounds__(256, 1) void iter_kernel(int src, int dst, float* __restrict__ out) {
    extern __shared__ float4 sm[];
    const int b = blockIdx.y;

    // Stage all points of this batch into SMEM (147456 B).
    const float4* gp = g_pts + b * NPTS;
    for (int i = threadIdx.x; i < NPTS; i += 256) sm[i] = gp[i];
    __syncthreads();

    const int q = blockIdx.x * 128 + (threadIdx.x >> 1);
    const int s = threadIdx.x & 1;

    float4 y = g_y[src][b * NPTS + q];
    const float tg = 2.0f * GG;
    const u64 qx2 = pk2(tg * y.x, tg * y.x);
    const u64 qy2 = pk2(tg * y.y, tg * y.y);
    const u64 qz2 = pk2(tg * y.z, tg * y.z);
    const float p = -GG * (y.x * y.x + y.y * y.y + y.z * y.z);
    const u64 pp = pk2(p, p);

    u64 accx = 0ull, accy = 0ull, accz = 0ull, accw = 0ull;  // bits 0 == {0.f,0.f}

    // Thread s handles pairs jp = 2*i + s. Lanes' LDS addresses are two
    // adjacent 32B chunks -> conflict-free 16-way broadcast.
    const float4* smp = sm + 2 * s;
    #pragma unroll 4
    for (int i = 0; i < NPTS / 4; i++) {      // 2304 steps, 2 points each
        float4 ab0 = smp[4 * i + 0];           // {x0,x1,y0,y1}
        float4 ab1 = smp[4 * i + 1];           // {z0,z1,b0,b1}
        u64 xx = pk2(ab0.x, ab0.y);
        u64 yy = pk2(ab0.z, ab0.w);
        u64 zz = pk2(ab1.x, ab1.y);
        u64 bb = pk2(ab1.z, ab1.w);
        u64 t = add2(bb, pp);
        t = fma2(qz2, zz, t);
        t = fma2(qy2, yy, t);
        t = fma2(qx2, xx, t);                  // t = arg for both points
        float t0, t1; upk2(t, t0, t1);
        u64 w2 = pk2(ex2f(t0), ex2f(t1));      // 2x MUFU EX2
        accx = fma2(w2, xx, accx);
        accy = fma2(w2, yy, accy);
        accz = fma2(w2, zz, accz);
        accw = add2(accw, w2);
    }

    float a0, a1;
    upk2(accx, a0, a1); float sx = a0 + a1;
    upk2(accy, a0, a1); float sy = a0 + a1;
    upk2(accz, a0, a1); float sz = a0 + a1;
    upk2(accw, a0, a1); float sw = a0 + a1;

    // Combine the two j-splits (partner lane differs only in bit 0).
    sx += __shfl_xor_sync(0xffffffffu, sx, 1);
    sy += __shfl_xor_sync(0xffffffffu, sy, 1);
    sz += __shfl_xor_sync(0xffffffffu, sz, 1);
    sw += __shfl_xor_sync(0xffffffffu, sw, 1);

    if (s == 0) {
        float inv = __fdividef(1.0f, sw);
        float nx = sx * inv, ny = sy * inv, nz = sz * inv;
        g_y[dst][b * NPTS + q] = make_float4(nx, ny, nz, 0.f);
        if (out) {
            out[(b * 3 + 0) * NPTS + q] = nx;
            out[(b * 3 + 1) * NPTS + q] = ny;
            out[(b * 3 + 2) * NPTS + q] = nz;
        }
    }
}

extern "C" void kernel_launch(void* const* d_in, const int* in_sizes, int n_in,
                              void* d_out, int out_size) {
    const float* x = (const float*)d_in[0];
    float* out = (float*)d_out;

    const size_t smem = (size_t)NPTS * sizeof(float4);  // 147456 B
    cudaFuncSetAttribute(iter_kernel, cudaFuncAttributeMaxDynamicSharedMemorySize, (int)smem);

    prep_kernel<<<(NB * NPTS + 255) / 256, 256>>>(x);

    dim3 grid(72, NB);
    for (int it = 0; it < 5; it++) {
        iter_kernel<<<grid, 256, smem>>>(it & 1, (it & 1) ^ 1, (it == 4) ? out : nullptr);
    }
}

// round 2
// speedup vs baseline: 1.0492x; 1.0492x over previous
#include <cuda_runtime.h>

// MeanShift: B=2, C=3, H=W=96 -> N=9216 points per batch, 5 iterations.
// w_ij = exp2( (2g*y_i).x_j + (-g*||x_j||^2) + (-g*||y_i||^2) ), g = 50/ln2.
// Inner loop: 8 f32x2 FMA-pipe ops + 2 MUFU EX2 per 2 points; the two pipes
// are balanced (~73.7K cyc/SM/iter each). This version fixes the latency
// bottleneck: 1024 threads (8 warps/SMSP), warp = 32 consecutive queries over
// ONE contiguous j-chunk -> all LDS are full-warp broadcasts, partials
// combined via a small SMEM reduction.

#define NPTS 9216
#define NB 2
#define GG 72.13475204444817f   // 50 / ln(2)
#define NSPLIT 8
#define CHUNK (NPTS / NSPLIT)   // 1152 points per chunk

typedef unsigned long long u64;

__device__ float4 g_pts[NB * NPTS];      // [2*jp+0]={x0,x1,y0,y1}, [2*jp+1]={z0,z1,b0,b1}
__device__ float4 g_y[2][NB * NPTS];

__device__ __forceinline__ float ex2f(float x) {
    float r; asm("ex2.approx.ftz.f32 %0, %1;" : "=f"(r) : "f"(x)); return r;
}
__device__ __forceinline__ u64 pk2(float a, float b) {
    u64 r; asm("mov.b64 %0, {%1,%2};" : "=l"(r) : "f"(a), "f"(b)); return r;
}
__device__ __forceinline__ void upk2(u64 v, float& a, float& b) {
    asm("mov.b64 {%0,%1}, %2;" : "=f"(a), "=f"(b) : "l"(v));
}
__device__ __forceinline__ u64 fma2(u64 a, u64 b, u64 c) {
    u64 d; asm("fma.rn.f32x2 %0, %1, %2, %3;" : "=l"(d) : "l"(a), "l"(b), "l"(c)); return d;
}
__device__ __forceinline__ u64 add2(u64 a, u64 b) {
    u64 d; asm("add.rn.f32x2 %0, %1, %2;" : "=l"(d) : "l"(a), "l"(b)); return d;
}

__global__ void prep_kernel(const float* __restrict__ x) {
    int idx = blockIdx.x * blockDim.x + threadIdx.x;
    if (idx >= NB * NPTS) return;
    int b = idx / NPTS, n = idx - b * NPTS;
    float px = x[(b * 3 + 0) * NPTS + n];
    float py = x[(b * 3 + 1) * NPTS + n];
    float pz = x[(b * 3 + 2) * NPTS + n];
    float bn = -GG * (px * px + py * py + pz * pz);
    int jp = n >> 1, l = n & 1;
    float* base = (float*)&g_pts[b * NPTS + 2 * jp];
    base[0 + l] = px;   // {x0,x1, y0,y1}
    base[2 + l] = py;
    base[4 + l] = pz;   // {z0,z1, b0,b1}
    base[6 + l] = bn;
    g_y[0][b * NPTS + n] = make_float4(px, py, pz, 0.f);
}

// Grid: (72 query-tiles, 2 batches), 1024 threads = 128 queries x 8 j-chunks.
__global__ __launch_bounds__(1024, 1) void iter_kernel(int src, int dst, float* __restrict__ out) {
    extern __shared__ float4 sm[];          // [0,NPTS): points, [NPTS,NPTS+1024): partials
    float4* psum = sm + NPTS;
    const int b = blockIdx.y;

    const float4* gp = g_pts + b * NPTS;
    for (int i = threadIdx.x; i < NPTS; i += 1024) sm[i] = gp[i];
    __syncthreads();

    const int q = threadIdx.x & 127;        // query within tile (32 consecutive per warp)
    const int s = threadIdx.x >> 7;         // j-chunk id (uniform within warp)
    const int qg = blockIdx.x * 128 + q;

    float4 y = g_y[src][b * NPTS + qg];
    const float tg = 2.0f * GG;
    const u64 qx2 = pk2(tg * y.x, tg * y.x);
    const u64 qy2 = pk2(tg * y.y, tg * y.y);
    const u64 qz2 = pk2(tg * y.z, tg * y.z);
    const float p = -GG * (y.x * y.x + y.y * y.y + y.z * y.z);
    const u64 pp = pk2(p, p);

    u64 accx = 0ull, accy = 0ull, accz = 0ull, accw = 0ull;

    // Whole warp walks the same chunk -> every LDS.128 is a 32-lane broadcast.
    const float4* smp = sm + s * (2 * CHUNK / 2);   // s * 1152 float4s
    #pragma unroll 4
    for (int i = 0; i < CHUNK / 2; i++) {           // 576 steps, 2 points each
        float4 ab0 = smp[2 * i + 0];                // {x0,x1,y0,y1}
        float4 ab1 = smp[2 * i + 1];                // {z0,z1,b0,b1}
        u64 xx = pk2(ab0.x, ab0.y);
        u64 yy = pk2(ab0.z, ab0.w);
        u64 zz = pk2(ab1.x, ab1.y);
        u64 bb = pk2(ab1.z, ab1.w);
        u64 t = add2(bb, pp);
        t = fma2(qz2, zz, t);
        t = fma2(qy2, yy, t);
        t = fma2(qx2, xx, t);                       // exp2 args for both points
        float t0, t1; upk2(t, t0, t1);
        u64 w2 = pk2(ex2f(t0), ex2f(t1));           // 2x MUFU EX2
        accx = fma2(w2, xx, accx);
        accy = fma2(w2, yy, accy);
        accz = fma2(w2, zz, accz);
        accw = add2(accw, w2);
    }

    float a0, a1;
    upk2(accx, a0, a1); float sx = a0 + a1;
    upk2(accy, a0, a1); float sy = a0 + a1;
    upk2(accz, a0, a1); float sz = a0 + a1;
    upk2(accw, a0, a1); float sw = a0 + a1;
    psum[threadIdx.x] = make_float4(sx, sy, sz, sw);
    __syncthreads();

    // Reduce the 8 chunk-partials per query.
    if (threadIdx.x < 128) {
        float4 a = psum[threadIdx.x];
        #pragma unroll
        for (int k = 1; k < NSPLIT; k++) {
            float4 p2 = psum[k * 128 + threadIdx.x];
            a.x += p2.x; a.y += p2.y; a.z += p2.z; a.w += p2.w;
        }
        float inv = __fdividef(1.0f, a.w);
        float nx = a.x * inv, ny = a.y * inv, nz = a.z * inv;
        int qi = blockIdx.x * 128 + threadIdx.x;
        g_y[dst][b * NPTS + qi] = make_float4(nx, ny, nz, 0.f);
        if (out) {
            out[(b * 3 + 0) * NPTS + qi] = nx;
            out[(b * 3 + 1) * NPTS + qi] = ny;
            out[(b * 3 + 2) * NPTS + qi] = nz;
        }
    }
}

extern "C" void kernel_launch(void* const* d_in, const int* in_sizes, int n_in,
                              void* d_out, int out_size) {
    const float* x = (const float*)d_in[0];
    float* out = (float*)d_out;

    const size_t smem = (size_t)(NPTS + 1024) * sizeof(float4);  // 163840 B
    cudaFuncSetAttribute(iter_kernel, cudaFuncAttributeMaxDynamicSharedMemorySize, (int)smem);

    prep_kernel<<<(NB * NPTS + 255) / 256, 256>>>(x);

    dim3 grid(72, NB);
    for (int it = 0; it < 5; it++) {
        iter_kernel<<<grid, 1024, smem>>>(it & 1, (it & 1) ^ 1, (it == 4) ? out : nullptr);
    }
}